// round 7
// baseline (speedup 1.0000x reference)
#include <cuda_runtime.h>
#include <cstdint>

#define B 8
#define A 110484
#define C 90
#define NN (A * C)          /* 9,943,560 per image */
#define N4 (NN / 4)         /* 2,485,890 */
#define TOPK 5000
#define MAXOUT 100
#define CAND_CAP 32768
#define SORT_CAP 16384
#define IOU_T 0.5f

#define SPEC_F 3.0f
#define KEY0 0xC0400000u    /* fkey(3.0f) */
#define HBINS 1024
#define HSHIFT 13
#define FBINS 4096
#define BINMAX 1024         /* per-bin sort capacity */

/* k_main tiling: 256 threads x 8 float4 per block */
#define MT 256
#define MV 8
#define MBLK (MT * MV)      /* 2048 float4 per block */

/* ------------------------- scratch (static, no allocs) ------------------ */
__device__ unsigned int       g_hist[B][HBINS];     /* fine bins, keys >= 3.0 */
__device__ unsigned int       g_binstart[B][HBINS]; /* descending prefix      */
__device__ unsigned int       g_thresh[B];
__device__ int                g_T[B];               /* threshold bin          */
__device__ int                g_ok[B];
__device__ int                g_cnt[B];
__device__ unsigned long long g_cand[B][CAND_CAP];
__device__ unsigned long long g_sorted[B][SORT_CAP];
__device__ float4             g_boxes[B][TOPK];
__device__ float              g_scores[B][TOPK];
__device__ int                g_cls[B][TOPK];
__device__ unsigned int       g_maxck[B];           /* fkey(max coord)        */

/* order-preserving float<->uint key */
__device__ __forceinline__ unsigned int fkey(float f) {
    unsigned int u = __float_as_uint(f);
    return (u & 0x80000000u) ? ~u : (u | 0x80000000u);
}
__device__ __forceinline__ float finv(unsigned int k) {
    unsigned int u = (k & 0x80000000u) ? (k ^ 0x80000000u) : ~k;
    return __uint_as_float(u);
}

/* decode one candidate; returns max box coord */
__device__ __forceinline__ float decode_one(int b, int pos, unsigned long long kv,
                                            const float4* __restrict__ bo4,
                                            const float4* __restrict__ an4) {
    unsigned int key = (unsigned int)(kv >> 32);
    unsigned int idx = 0xFFFFFFFFu - (unsigned int)(kv & 0xFFFFFFFFu);
    float val = finv(key);
    unsigned int a = idx / (unsigned int)C;
    int cidx = (int)(idx - a * (unsigned int)C);
    float4 rc = bo4[(size_t)b * A + a];
    float4 an = an4[a];
    float ycA = (an.x + an.z) * 0.5f;
    float xcA = (an.y + an.w) * 0.5f;
    float ha = an.z - an.x;
    float wa = an.w - an.y;
    float w = expf(rc.w) * wa;
    float h = expf(rc.z) * ha;
    float yc = rc.x * ha + ycA;
    float xc = rc.y * wa + xcA;
    float4 box = make_float4(xc - w * 0.5f, yc - h * 0.5f,
                             xc + w * 0.5f, yc + h * 0.5f);
    g_boxes[b][pos] = box;
    g_scores[b][pos] = 1.f / (1.f + expf(-val));
    g_cls[b][pos] = cidx;
    return fmaxf(fmaxf(box.x, box.y), fmaxf(box.z, box.w));
}

/* ------------------------------ init ------------------------------------ */
__global__ void __launch_bounds__(HBINS) k_init() {
    const int b = blockIdx.x;
    g_hist[b][threadIdx.x] = 0;
    if (threadIdx.x == 0) { g_cnt[b] = 0; g_maxck[b] = 0u; }
}

/* ------------- pass 1: fused speculative collect + fine hist ------------ */
__device__ __forceinline__ void proc_elem(float val, unsigned int eidx, int b) {
    if (val >= SPEC_F) {
        unsigned int key = __float_as_uint(val) | 0x80000000u; /* val>0 */
        unsigned int bin = (key - KEY0) >> HSHIFT;
        if (bin > HBINS - 1) bin = HBINS - 1;
        atomicAdd(&g_hist[b][bin], 1u);
        int pos = atomicAdd(&g_cnt[b], 1);
        if (pos < CAND_CAP)
            g_cand[b][pos] =
                ((unsigned long long)key << 32) | (0xFFFFFFFFu - eidx);
    }
}
__device__ __forceinline__ void proc_vec(float4 v, unsigned int i, int b) {
    unsigned int base = 4u * i;
    proc_elem(v.x, base + 0u, b);
    proc_elem(v.y, base + 1u, b);
    proc_elem(v.z, base + 2u, b);
    proc_elem(v.w, base + 3u, b);
}

__global__ void __launch_bounds__(MT) k_main(const float* __restrict__ cls) {
    const int b = blockIdx.y;
    const float4* __restrict__ p = (const float4*)(cls + (size_t)b * NN);
    const unsigned int i0 = blockIdx.x * (unsigned)MBLK + threadIdx.x;
    float4 v[MV];
    const float4 neg = make_float4(-1e30f, -1e30f, -1e30f, -1e30f);
    if ((blockIdx.x + 1) * (unsigned)MBLK <= (unsigned)N4) {
        #pragma unroll
        for (int k = 0; k < MV; k++) v[k] = p[i0 + k * MT];
    } else {
        #pragma unroll
        for (int k = 0; k < MV; k++)
            v[k] = (i0 + k * MT < (unsigned)N4) ? p[i0 + k * MT] : neg;
    }
    float m = -1e30f;
    #pragma unroll
    for (int k = 0; k < MV; k++)
        m = fmaxf(m, fmaxf(fmaxf(v[k].x, v[k].y), fmaxf(v[k].z, v[k].w)));
    if (m >= SPEC_F) {  /* rare */
        #pragma unroll
        for (int k = 0; k < MV; k++) proc_vec(v[k], i0 + k * MT, b);
    }
}

/* --- pass 2: exact threshold + descending prefix + scatter (fused) ------ */
__global__ void __launch_bounds__(HBINS) k_thresh_scatter() {
    const int b = blockIdx.x;
    const int tid = threadIdx.x;
    __shared__ unsigned int wsum[32], woff[32], wmax[32];
    __shared__ unsigned int binstart_s[HBINS];
    __shared__ unsigned int binoff_s[HBINS];
    __shared__ int rT;
    __shared__ unsigned int totGe;
    __shared__ int ok_s;
    __shared__ unsigned int th_s;

    /* hist in descending-key order */
    unsigned int v = g_hist[b][HBINS - 1 - tid];
    unsigned int lane = tid & 31u, w = tid >> 5;
    binoff_s[tid] = 0;
    unsigned int incl = v;
    #pragma unroll
    for (int o = 1; o < 32; o <<= 1) {
        unsigned int t = __shfl_up_sync(0xffffffffu, incl, o);
        if (lane >= (unsigned)o) incl += t;
    }
    if (lane == 31) wsum[w] = incl;
    if (tid == 0) { rT = -1; totGe = 0; }
    __syncthreads();
    if (tid == 0) {
        unsigned int acc = 0;
        for (int i = 0; i < 32; i++) { woff[i] = acc; acc += wsum[i]; }
    }
    __syncthreads();
    unsigned int excl = woff[w] + incl - v;
    binstart_s[HBINS - 1 - tid] = excl;
    g_binstart[b][HBINS - 1 - tid] = excl;
    if (v > 0 && excl < TOPK && excl + v >= TOPK) { rT = tid; totGe = excl + v; }
    __syncthreads();
    int r = rT;
    unsigned int mv = (r >= 0 && tid <= r) ? v : 0;
    #pragma unroll
    for (int o = 16; o > 0; o >>= 1)
        mv = max(mv, __shfl_down_sync(0xffffffffu, mv, o));
    if (lane == 0) wmax[w] = mv;
    __syncthreads();
    if (tid == 0) {
        unsigned int mb = 0;
        for (int i = 0; i < 32; i++) mb = max(mb, wmax[i]);
        int cnt = g_cnt[b];
        int ok = (r >= 0) && (cnt <= CAND_CAP) && (totGe <= SORT_CAP) &&
                 (mb <= BINMAX);
        g_ok[b] = ok;
        ok_s = ok;
        if (ok) {
            int binT = HBINS - 1 - r;
            g_T[b] = binT;
            th_s = KEY0 + ((unsigned int)binT << HSHIFT);
            g_thresh[b] = th_s;
        }
    }
    __syncthreads();
    if (!ok_s) return;

    /* scatter candidates to bin slot ranges (smem cursors) */
    const unsigned int th = th_s;
    int cnt = g_cnt[b];
    if (cnt > CAND_CAP) cnt = CAND_CAP;
    for (int i = tid; i < cnt; i += HBINS) {
        unsigned long long kv = g_cand[b][i];
        unsigned int key = (unsigned int)(kv >> 32);
        if (key >= th) {
            unsigned int bin = (key - KEY0) >> HSHIFT;
            if (bin > HBINS - 1) bin = HBINS - 1;
            unsigned int pos = binstart_s[bin] + atomicAdd(&binoff_s[bin], 1u);
            g_sorted[b][pos] = kv;
        }
    }
}

/* ------- fallback: entire pipeline in one block per image (never hot) ---- */
__global__ void __launch_bounds__(1024) k_fallback(const float* __restrict__ cls,
                                                   const float* __restrict__ box_out,
                                                   const float* __restrict__ anchors) {
    extern __shared__ unsigned long long sdyn[];  /* 128 KB */
    const int b = blockIdx.x;
    if (g_ok[b]) return;
    const int tid = threadIdx.x;
    unsigned int* h = (unsigned int*)sdyn;  /* FBINS counters (reused later) */
    for (int i = tid; i < FBINS; i += 1024) h[i] = 0;
    __syncthreads();
    const float4* p = (const float4*)(cls + (size_t)b * NN);
    for (int i = tid; i < N4; i += 1024) {
        float4 v = p[i];
        atomicAdd(&h[fkey(v.x) >> 20], 1u);
        atomicAdd(&h[fkey(v.y) >> 20], 1u);
        atomicAdd(&h[fkey(v.z) >> 20], 1u);
        atomicAdd(&h[fkey(v.w) >> 20], 1u);
    }
    __syncthreads();
    __shared__ unsigned int th_sh;
    __shared__ int scnt;
    if (tid == 0) {
        unsigned int acc = 0;
        int T = 0;
        for (int bin = FBINS - 1; bin >= 0; bin--) {
            acc += h[bin];
            if (acc >= TOPK) { T = bin; break; }
        }
        th_sh = ((unsigned int)T) << 20;
        scnt = 0;
    }
    __syncthreads();
    const unsigned int th = th_sh;
    __syncthreads();  /* all threads read th/hist before sdyn reuse */
    for (int i = tid; i < N4; i += 1024) {
        float4 v = p[i];
        unsigned int base = 4u * (unsigned int)i;
        float vals[4] = {v.x, v.y, v.z, v.w};
        #pragma unroll
        for (int e = 0; e < 4; e++) {
            unsigned int k = fkey(vals[e]);
            if (k >= th) {
                int pos = atomicAdd(&scnt, 1);
                if (pos < SORT_CAP)
                    sdyn[pos] = ((unsigned long long)k << 32) |
                                (0xFFFFFFFFu - (base + (unsigned)e));
            }
        }
    }
    __syncthreads();
    int c2 = scnt;
    if (c2 > SORT_CAP) c2 = SORT_CAP;
    const int nn = (c2 <= 8192) ? 8192 : SORT_CAP;
    for (int i = c2 + tid; i < nn; i += 1024) sdyn[i] = 0ULL;
    __syncthreads();
    for (unsigned int k = 2; k <= (unsigned int)nn; k <<= 1) {
        for (unsigned int j = k >> 1; j > 0; j >>= 1) {
            for (int i = tid; i < nn; i += 1024) {
                unsigned int ixj = (unsigned int)i ^ j;
                if (ixj > (unsigned int)i) {
                    bool up = ((i & k) == 0);
                    unsigned long long a = sdyn[i], c = sdyn[ixj];
                    bool sw = up ? (a < c) : (a > c);
                    if (sw) { sdyn[i] = c; sdyn[ixj] = a; }
                }
            }
            __syncthreads();
        }
    }
    /* decode top-TOPK */
    const float4* bo4 = (const float4*)box_out;
    const float4* an4 = (const float4*)anchors;
    float localmax = -1e30f;
    for (int i = tid; i < TOPK; i += 1024) {
        unsigned long long kv = sdyn[i];
        if (kv == 0ULL) {
            g_boxes[b][i] = make_float4(0.f, 0.f, 0.f, 0.f);
            g_scores[b][i] = 0.f;
            g_cls[b][i] = 0;
        } else {
            localmax = fmaxf(localmax, decode_one(b, i, kv, bo4, an4));
        }
    }
    #pragma unroll
    for (int o = 16; o > 0; o >>= 1)
        localmax = fmaxf(localmax, __shfl_xor_sync(0xffffffffu, localmax, o));
    if ((tid & 31) == 0) atomicMax(&g_maxck[b], fkey(localmax));
}

/* --------- pass 3: per-bin bitonic sort + fused decode ------------------- */
__global__ void __launch_bounds__(128) k_binsort(const float* __restrict__ box_out,
                                                 const float* __restrict__ anchors) {
    const int bin = blockIdx.x;
    const int b = blockIdx.y;
    if (!g_ok[b]) return;
    if (bin < g_T[b]) return;
    const unsigned int c = g_hist[b][bin];
    if (c == 0) return;
    const unsigned int start = g_binstart[b][bin];
    if (start >= TOPK) return;
    __shared__ unsigned long long s[BINMAX];
    unsigned int n = 1;
    while (n < c) n <<= 1;
    const int tid = threadIdx.x;
    for (unsigned int i = tid; i < n; i += 128)
        s[i] = (i < c) ? g_sorted[b][start + i] : 0ULL;
    __syncthreads();
    for (unsigned int k = 2; k <= n; k <<= 1) {
        for (unsigned int j = k >> 1; j > 0; j >>= 1) {
            for (unsigned int i = tid; i < n; i += 128) {
                unsigned int ixj = i ^ j;
                if (ixj > i) {
                    bool up = ((i & k) == 0);
                    unsigned long long a = s[i], cc = s[ixj];
                    bool sw = up ? (a < cc) : (a > cc);
                    if (sw) { s[i] = cc; s[ixj] = a; }
                }
            }
            __syncthreads();
        }
    }
    /* decode global positions < TOPK directly from smem */
    const float4* bo4 = (const float4*)box_out;
    const float4* an4 = (const float4*)anchors;
    float localmax = -1e30f;
    for (unsigned int i = tid; i < c; i += 128) {
        unsigned int pos = start + i;
        if (pos < TOPK)
            localmax = fmaxf(localmax, decode_one(b, (int)pos, s[i], bo4, an4));
    }
    #pragma unroll
    for (int o = 16; o > 0; o >>= 1)
        localmax = fmaxf(localmax, __shfl_xor_sync(0xffffffffu, localmax, o));
    if ((tid & 31) == 0) atomicMax(&g_maxck[b], fkey(localmax));
}

/* ---------------------- pass 4: greedy NMS + output ---------------------- */
__global__ void k_nms(const float* __restrict__ img_scale, float* __restrict__ out) {
    const int b = blockIdx.x;
    const int l = threadIdx.x; /* one warp per image */
    __shared__ float4 skb[MAXOUT + 32];
    __shared__ float ska[MAXOUT + 32];
    __shared__ float4 st_box[64];
    __shared__ float st_sc[64];
    __shared__ int st_cl[64];

    const float maxc1 = finv(g_maxck[b]) + 1.0f;
    const float scale = img_scale[b];
    int K = 0;

    for (int base = 0; base < TOPK && K < MAXOUT; base += 64) {
        int m = TOPK - base;
        if (m > 64) m = 64;
        for (int t = l; t < m; t += 32) {
            st_box[t] = g_boxes[b][base + t];
            st_sc[t] = g_scores[b][base + t];
            st_cl[t] = g_cls[b][base + t];
        }
        __syncwarp();
        for (int ii = 0; ii < m; ii++) {
            if (K >= MAXOUT) break;
            float4 bx = st_box[ii];
            int cidx = st_cl[ii];
            float off = (float)cidx * maxc1;
            float4 nb = make_float4(bx.x + off, bx.y + off, bx.z + off, bx.w + off);
            float areaC = (nb.z - nb.x) * (nb.w - nb.y);
            bool ov = false;
            for (int sidx = l; sidx < K; sidx += 32) {
                float4 kb = skb[sidx];
                float w = fminf(nb.z, kb.z) - fmaxf(nb.x, kb.x);
                float h = fminf(nb.w, kb.w) - fmaxf(nb.y, kb.y);
                w = fmaxf(w, 0.f);
                h = fmaxf(h, 0.f);
                float inter = w * h;
                if (inter > 0.f) {
                    float uni = areaC + ska[sidx] - inter;
                    if (inter / uni > IOU_T) ov = true;
                }
            }
            if (!__any_sync(0xffffffffu, ov)) {
                if (l == 0) {
                    skb[K] = nb;
                    ska[K] = areaC;
                    float* o = out + ((size_t)b * MAXOUT + K) * 6;
                    o[0] = bx.x * scale;
                    o[1] = bx.y * scale;
                    o[2] = bx.z * scale;
                    o[3] = bx.w * scale;
                    o[4] = st_sc[ii];
                    o[5] = (float)(cidx + 1);
                }
                K++;
                __syncwarp();
            }
        }
        __syncwarp();
    }
    for (int r = l; r < MAXOUT; r += 32) {
        if (r >= K) {
            float* o = out + ((size_t)b * MAXOUT + r) * 6;
            o[0] = 0.f; o[1] = 0.f; o[2] = 0.f; o[3] = 0.f;
            o[4] = 0.f; o[5] = -1.f;
        }
    }
}

/* ------------------------------ launcher -------------------------------- */
extern "C" void kernel_launch(void* const* d_in, const int* in_sizes, int n_in,
                              void* d_out, int out_size) {
    const float* cls = nullptr;
    const float* box = nullptr;
    const float* anc = nullptr;
    const float* scl = nullptr;
    for (int i = 0; i < n_in; i++) {
        long long sz = in_sizes[i];
        if (sz == (long long)B * NN) cls = (const float*)d_in[i];
        else if (sz == (long long)B * A * 4) box = (const float*)d_in[i];
        else if (sz == (long long)A * 4) anc = (const float*)d_in[i];
        else if (sz == B) scl = (const float*)d_in[i];
    }
    float* out = (float*)d_out;

    static bool attr_set = false;
    if (!attr_set) {
        cudaFuncSetAttribute(k_fallback,
                             cudaFuncAttributeMaxDynamicSharedMemorySize,
                             SORT_CAP * (int)sizeof(unsigned long long));
        attr_set = true;
    }

    k_init<<<B, HBINS>>>();
    {
        dim3 grid((N4 + MBLK - 1) / MBLK, B);
        k_main<<<grid, MT>>>(cls);
    }
    k_thresh_scatter<<<B, HBINS>>>();
    k_fallback<<<B, 1024, SORT_CAP * sizeof(unsigned long long)>>>(cls, box, anc);
    {
        dim3 grid(HBINS, B);
        k_binsort<<<grid, 128>>>(box, anc);
    }
    k_nms<<<B, 32>>>(scl, out);
}

// round 8
// speedup vs baseline: 1.0210x; 1.0210x over previous
#include <cuda_runtime.h>
#include <cstdint>

#define B 8
#define A 110484
#define C 90
#define NN (A * C)          /* 9,943,560 per image */
#define N4 (NN / 4)         /* 2,485,890 */
#define TOPK 5000
#define MAXOUT 100
#define CAND_CAP 32768
#define SORT_CAP 16384
#define IOU_T 0.5f

#define SPEC_F 3.0f
#define KEY0 0xC0400000u    /* fkey(3.0f) */
#define HBINS 1024
#define HSHIFT 13
#define FBINS 4096
#define BINMAX 1024         /* per-bin sort capacity */

/* k_main tiling: 256 threads x 4 float4 per block (proven R6 config) */
#define MT 256
#define MV 4
#define MBLK (MT * MV)      /* 1024 float4 per block */

/* ------------------------- scratch (static, no allocs) ------------------ */
/* INVARIANT: g_hist, g_cnt, g_maxck are zero at the start of every launch:
   zero-initialized at load, and every launch restores them to zero. */
__device__ unsigned int       g_hist[B][HBINS];     /* fine bins, keys >= 3.0 */
__device__ unsigned int       g_binpack[B][HBINS];  /* (count<<16)|start      */
__device__ unsigned int       g_thresh[B];
__device__ int                g_T[B];               /* threshold bin          */
__device__ int                g_ok[B];
__device__ int                g_cnt[B];
__device__ unsigned long long g_cand[B][CAND_CAP];
__device__ unsigned long long g_sorted[B][SORT_CAP];
__device__ float4             g_boxes[B][TOPK];
__device__ float              g_scores[B][TOPK];
__device__ int                g_cls[B][TOPK];
__device__ unsigned int       g_maxck[B];           /* fkey(max coord)        */

/* order-preserving float<->uint key */
__device__ __forceinline__ unsigned int fkey(float f) {
    unsigned int u = __float_as_uint(f);
    return (u & 0x80000000u) ? ~u : (u | 0x80000000u);
}
__device__ __forceinline__ float finv(unsigned int k) {
    unsigned int u = (k & 0x80000000u) ? (k ^ 0x80000000u) : ~k;
    return __uint_as_float(u);
}

/* decode one candidate; returns max box coord */
__device__ __forceinline__ float decode_one(int b, int pos, unsigned long long kv,
                                            const float4* __restrict__ bo4,
                                            const float4* __restrict__ an4) {
    unsigned int key = (unsigned int)(kv >> 32);
    unsigned int idx = 0xFFFFFFFFu - (unsigned int)(kv & 0xFFFFFFFFu);
    float val = finv(key);
    unsigned int a = idx / (unsigned int)C;
    int cidx = (int)(idx - a * (unsigned int)C);
    float4 rc = bo4[(size_t)b * A + a];
    float4 an = an4[a];
    float ycA = (an.x + an.z) * 0.5f;
    float xcA = (an.y + an.w) * 0.5f;
    float ha = an.z - an.x;
    float wa = an.w - an.y;
    float w = expf(rc.w) * wa;
    float h = expf(rc.z) * ha;
    float yc = rc.x * ha + ycA;
    float xc = rc.y * wa + xcA;
    float4 box = make_float4(xc - w * 0.5f, yc - h * 0.5f,
                             xc + w * 0.5f, yc + h * 0.5f);
    g_boxes[b][pos] = box;
    g_scores[b][pos] = 1.f / (1.f + expf(-val));
    g_cls[b][pos] = cidx;
    return fmaxf(fmaxf(box.x, box.y), fmaxf(box.z, box.w));
}

/* ------------- pass 1: fused speculative collect + fine hist ------------ */
__device__ __forceinline__ void proc_elem(float val, unsigned int eidx, int b) {
    if (val >= SPEC_F) {
        unsigned int key = __float_as_uint(val) | 0x80000000u; /* val>0 */
        unsigned int bin = (key - KEY0) >> HSHIFT;
        if (bin > HBINS - 1) bin = HBINS - 1;
        atomicAdd(&g_hist[b][bin], 1u);
        int pos = atomicAdd(&g_cnt[b], 1);
        if (pos < CAND_CAP)
            g_cand[b][pos] =
                ((unsigned long long)key << 32) | (0xFFFFFFFFu - eidx);
    }
}
__device__ __forceinline__ void proc_vec(float4 v, unsigned int i, int b) {
    unsigned int base = 4u * i;
    proc_elem(v.x, base + 0u, b);
    proc_elem(v.y, base + 1u, b);
    proc_elem(v.z, base + 2u, b);
    proc_elem(v.w, base + 3u, b);
}

__global__ void __launch_bounds__(MT) k_main(const float* __restrict__ cls) {
    const int b = blockIdx.y;
    const float4* __restrict__ p = (const float4*)(cls + (size_t)b * NN);
    const unsigned int i0 = blockIdx.x * (unsigned)MBLK + threadIdx.x;
    float4 v0, v1, v2, v3;
    const float4 neg = make_float4(-1e30f, -1e30f, -1e30f, -1e30f);
    if ((blockIdx.x + 1) * (unsigned)MBLK <= (unsigned)N4) {
        v0 = p[i0];
        v1 = p[i0 + MT];
        v2 = p[i0 + 2 * MT];
        v3 = p[i0 + 3 * MT];
    } else {
        v0 = (i0          < (unsigned)N4) ? p[i0]          : neg;
        v1 = (i0 +   MT   < (unsigned)N4) ? p[i0 + MT]     : neg;
        v2 = (i0 + 2 * MT < (unsigned)N4) ? p[i0 + 2 * MT] : neg;
        v3 = (i0 + 3 * MT < (unsigned)N4) ? p[i0 + 3 * MT] : neg;
    }
    float m0 = fmaxf(fmaxf(v0.x, v0.y), fmaxf(v0.z, v0.w));
    float m1 = fmaxf(fmaxf(v1.x, v1.y), fmaxf(v1.z, v1.w));
    float m2 = fmaxf(fmaxf(v2.x, v2.y), fmaxf(v2.z, v2.w));
    float m3 = fmaxf(fmaxf(v3.x, v3.y), fmaxf(v3.z, v3.w));
    float m = fmaxf(fmaxf(m0, m1), fmaxf(m2, m3));
    if (m >= SPEC_F) {  /* ~2% of threads */
        proc_vec(v0, i0, b);
        proc_vec(v1, i0 + MT, b);
        proc_vec(v2, i0 + 2 * MT, b);
        proc_vec(v3, i0 + 3 * MT, b);
    }
}

/* --- pass 2: threshold + descending prefix + scatter; resets hist/cnt --- */
__global__ void __launch_bounds__(HBINS) k_thresh_scatter() {
    const int b = blockIdx.x;
    const int tid = threadIdx.x;
    __shared__ unsigned int wsum[32], woff[32], wmax[32];
    __shared__ unsigned int binstart_s[HBINS];
    __shared__ unsigned int binoff_s[HBINS];
    __shared__ int rT;
    __shared__ unsigned int totGe;
    __shared__ int ok_s;
    __shared__ unsigned int th_s;
    __shared__ int cnt_s;

    /* hist in descending-key order; zero it for the next launch */
    unsigned int v = g_hist[b][HBINS - 1 - tid];
    g_hist[b][HBINS - 1 - tid] = 0u;
    unsigned int lane = tid & 31u, w = tid >> 5;
    binoff_s[tid] = 0;
    unsigned int incl = v;
    #pragma unroll
    for (int o = 1; o < 32; o <<= 1) {
        unsigned int t = __shfl_up_sync(0xffffffffu, incl, o);
        if (lane >= (unsigned)o) incl += t;
    }
    if (lane == 31) wsum[w] = incl;
    if (tid == 0) { rT = -1; totGe = 0; }
    __syncthreads();
    if (tid == 0) {
        unsigned int acc = 0;
        for (int i = 0; i < 32; i++) { woff[i] = acc; acc += wsum[i]; }
    }
    __syncthreads();
    unsigned int excl = woff[w] + incl - v;
    binstart_s[HBINS - 1 - tid] = excl;
    g_binpack[b][HBINS - 1 - tid] = (v << 16) | excl;  /* count|start */
    if (v > 0 && excl < TOPK && excl + v >= TOPK) { rT = tid; totGe = excl + v; }
    __syncthreads();
    int r = rT;
    unsigned int mv = (r >= 0 && tid <= r) ? v : 0;
    #pragma unroll
    for (int o = 16; o > 0; o >>= 1)
        mv = max(mv, __shfl_down_sync(0xffffffffu, mv, o));
    if (lane == 0) wmax[w] = mv;
    __syncthreads();
    if (tid == 0) {
        unsigned int mb = 0;
        for (int i = 0; i < 32; i++) mb = max(mb, wmax[i]);
        int cnt = g_cnt[b];
        g_cnt[b] = 0;                 /* reset for next launch */
        cnt_s = cnt;
        int ok = (r >= 0) && (cnt <= CAND_CAP) && (totGe <= SORT_CAP) &&
                 (mb <= BINMAX);
        g_ok[b] = ok;
        ok_s = ok;
        if (ok) {
            int binT = HBINS - 1 - r;
            g_T[b] = binT;
            th_s = KEY0 + ((unsigned int)binT << HSHIFT);
            g_thresh[b] = th_s;
        }
    }
    __syncthreads();
    if (!ok_s) return;

    /* scatter candidates to bin slot ranges (smem cursors) */
    const unsigned int th = th_s;
    int cnt = cnt_s;
    for (int i = tid; i < cnt; i += HBINS) {
        unsigned long long kv = g_cand[b][i];
        unsigned int key = (unsigned int)(kv >> 32);
        if (key >= th) {
            unsigned int bin = (key - KEY0) >> HSHIFT;
            if (bin > HBINS - 1) bin = HBINS - 1;
            unsigned int pos = binstart_s[bin] + atomicAdd(&binoff_s[bin], 1u);
            g_sorted[b][pos] = kv;
        }
    }
}

/* ------- fallback: entire pipeline in one block per image (never hot) ---- */
__global__ void __launch_bounds__(1024) k_fallback(const float* __restrict__ cls,
                                                   const float* __restrict__ box_out,
                                                   const float* __restrict__ anchors) {
    extern __shared__ unsigned long long sdyn[];  /* 128 KB */
    const int b = blockIdx.x;
    if (g_ok[b]) return;
    const int tid = threadIdx.x;
    unsigned int* h = (unsigned int*)sdyn;  /* FBINS counters (reused later) */
    for (int i = tid; i < FBINS; i += 1024) h[i] = 0;
    __syncthreads();
    const float4* p = (const float4*)(cls + (size_t)b * NN);
    for (int i = tid; i < N4; i += 1024) {
        float4 v = p[i];
        atomicAdd(&h[fkey(v.x) >> 20], 1u);
        atomicAdd(&h[fkey(v.y) >> 20], 1u);
        atomicAdd(&h[fkey(v.z) >> 20], 1u);
        atomicAdd(&h[fkey(v.w) >> 20], 1u);
    }
    __syncthreads();
    __shared__ unsigned int th_sh;
    __shared__ int scnt;
    if (tid == 0) {
        unsigned int acc = 0;
        int T = 0;
        for (int bin = FBINS - 1; bin >= 0; bin--) {
            acc += h[bin];
            if (acc >= TOPK) { T = bin; break; }
        }
        th_sh = ((unsigned int)T) << 20;
        scnt = 0;
    }
    __syncthreads();
    const unsigned int th = th_sh;
    __syncthreads();  /* all threads read th before sdyn reuse */
    for (int i = tid; i < N4; i += 1024) {
        float4 v = p[i];
        unsigned int base = 4u * (unsigned int)i;
        float vals[4] = {v.x, v.y, v.z, v.w};
        #pragma unroll
        for (int e = 0; e < 4; e++) {
            unsigned int k = fkey(vals[e]);
            if (k >= th) {
                int pos = atomicAdd(&scnt, 1);
                if (pos < SORT_CAP)
                    sdyn[pos] = ((unsigned long long)k << 32) |
                                (0xFFFFFFFFu - (base + (unsigned)e));
            }
        }
    }
    __syncthreads();
    int c2 = scnt;
    if (c2 > SORT_CAP) c2 = SORT_CAP;
    const int nn = (c2 <= 8192) ? 8192 : SORT_CAP;
    for (int i = c2 + tid; i < nn; i += 1024) sdyn[i] = 0ULL;
    __syncthreads();
    for (unsigned int k = 2; k <= (unsigned int)nn; k <<= 1) {
        for (unsigned int j = k >> 1; j > 0; j >>= 1) {
            for (int i = tid; i < nn; i += 1024) {
                unsigned int ixj = (unsigned int)i ^ j;
                if (ixj > (unsigned int)i) {
                    bool up = ((i & k) == 0);
                    unsigned long long a = sdyn[i], c = sdyn[ixj];
                    bool sw = up ? (a < c) : (a > c);
                    if (sw) { sdyn[i] = c; sdyn[ixj] = a; }
                }
            }
            __syncthreads();
        }
    }
    const float4* bo4 = (const float4*)box_out;
    const float4* an4 = (const float4*)anchors;
    float localmax = -1e30f;
    for (int i = tid; i < TOPK; i += 1024) {
        unsigned long long kv = sdyn[i];
        if (kv == 0ULL) {
            g_boxes[b][i] = make_float4(0.f, 0.f, 0.f, 0.f);
            g_scores[b][i] = 0.f;
            g_cls[b][i] = 0;
        } else {
            localmax = fmaxf(localmax, decode_one(b, i, kv, bo4, an4));
        }
    }
    #pragma unroll
    for (int o = 16; o > 0; o >>= 1)
        localmax = fmaxf(localmax, __shfl_xor_sync(0xffffffffu, localmax, o));
    if ((tid & 31) == 0) atomicMax(&g_maxck[b], fkey(localmax));
}

/* --------- pass 3: per-bin bitonic sort + fused decode ------------------- */
__global__ void __launch_bounds__(128) k_binsort(const float* __restrict__ box_out,
                                                 const float* __restrict__ anchors) {
    const int b = blockIdx.y;
    if (!g_ok[b]) return;
    const int T = g_T[b];
    const int tid = threadIdx.x;
    const float4* bo4 = (const float4*)box_out;
    const float4* an4 = (const float4*)anchors;
    __shared__ unsigned long long s[BINMAX];
    float localmax = -1e30f;

    for (int bin = T + blockIdx.x; bin < HBINS; bin += gridDim.x) {
        unsigned int pk = g_binpack[b][bin];
        unsigned int c = pk >> 16;
        if (c == 0) continue;
        unsigned int start = pk & 0xFFFFu;
        unsigned int n = 1;
        while (n < c) n <<= 1;
        for (unsigned int i = tid; i < n; i += 128)
            s[i] = (i < c) ? g_sorted[b][start + i] : 0ULL;
        __syncthreads();
        for (unsigned int k = 2; k <= n; k <<= 1) {
            for (unsigned int j = k >> 1; j > 0; j >>= 1) {
                for (unsigned int i = tid; i < n; i += 128) {
                    unsigned int ixj = i ^ j;
                    if (ixj > i) {
                        bool up = ((i & k) == 0);
                        unsigned long long a = s[i], cc = s[ixj];
                        bool sw = up ? (a < cc) : (a > cc);
                        if (sw) { s[i] = cc; s[ixj] = a; }
                    }
                }
                __syncthreads();
            }
        }
        for (unsigned int i = tid; i < c; i += 128) {
            unsigned int pos = start + i;
            if (pos < TOPK)
                localmax = fmaxf(localmax, decode_one(b, (int)pos, s[i], bo4, an4));
        }
        __syncthreads();  /* s[] reused next iteration */
    }
    #pragma unroll
    for (int o = 16; o > 0; o >>= 1)
        localmax = fmaxf(localmax, __shfl_xor_sync(0xffffffffu, localmax, o));
    if ((tid & 31) == 0) atomicMax(&g_maxck[b], fkey(localmax));
}

/* ------------- pass 4: greedy NMS + output; resets g_maxck --------------- */
__global__ void k_nms(const float* __restrict__ img_scale, float* __restrict__ out) {
    const int b = blockIdx.x;
    const int l = threadIdx.x; /* one warp per image */
    __shared__ float4 skb[MAXOUT + 32];
    __shared__ float ska[MAXOUT + 32];
    __shared__ float4 st_box[64];
    __shared__ float st_sc[64];
    __shared__ int st_cl[64];

    const float maxc1 = finv(g_maxck[b]) + 1.0f;
    if (l == 0) g_maxck[b] = 0u;   /* reset for next launch */
    const float scale = img_scale[b];
    int K = 0;

    for (int base = 0; base < TOPK && K < MAXOUT; base += 64) {
        int m = TOPK - base;
        if (m > 64) m = 64;
        for (int t = l; t < m; t += 32) {
            st_box[t] = g_boxes[b][base + t];
            st_sc[t] = g_scores[b][base + t];
            st_cl[t] = g_cls[b][base + t];
        }
        __syncwarp();
        for (int ii = 0; ii < m; ii++) {
            if (K >= MAXOUT) break;
            float4 bx = st_box[ii];
            int cidx = st_cl[ii];
            float off = (float)cidx * maxc1;
            float4 nb = make_float4(bx.x + off, bx.y + off, bx.z + off, bx.w + off);
            float areaC = (nb.z - nb.x) * (nb.w - nb.y);
            bool ov = false;
            for (int sidx = l; sidx < K; sidx += 32) {
                float4 kb = skb[sidx];
                float w = fminf(nb.z, kb.z) - fmaxf(nb.x, kb.x);
                float h = fminf(nb.w, kb.w) - fmaxf(nb.y, kb.y);
                w = fmaxf(w, 0.f);
                h = fmaxf(h, 0.f);
                float inter = w * h;
                if (inter > 0.f) {
                    float uni = areaC + ska[sidx] - inter;
                    if (inter / uni > IOU_T) ov = true;
                }
            }
            if (!__any_sync(0xffffffffu, ov)) {
                if (l == 0) {
                    skb[K] = nb;
                    ska[K] = areaC;
                    float* o = out + ((size_t)b * MAXOUT + K) * 6;
                    o[0] = bx.x * scale;
                    o[1] = bx.y * scale;
                    o[2] = bx.z * scale;
                    o[3] = bx.w * scale;
                    o[4] = st_sc[ii];
                    o[5] = (float)(cidx + 1);
                }
                K++;
                __syncwarp();
            }
        }
        __syncwarp();
    }
    for (int r = l; r < MAXOUT; r += 32) {
        if (r >= K) {
            float* o = out + ((size_t)b * MAXOUT + r) * 6;
            o[0] = 0.f; o[1] = 0.f; o[2] = 0.f; o[3] = 0.f;
            o[4] = 0.f; o[5] = -1.f;
        }
    }
}

/* ------------------------------ launcher -------------------------------- */
extern "C" void kernel_launch(void* const* d_in, const int* in_sizes, int n_in,
                              void* d_out, int out_size) {
    const float* cls = nullptr;
    const float* box = nullptr;
    const float* anc = nullptr;
    const float* scl = nullptr;
    for (int i = 0; i < n_in; i++) {
        long long sz = in_sizes[i];
        if (sz == (long long)B * NN) cls = (const float*)d_in[i];
        else if (sz == (long long)B * A * 4) box = (const float*)d_in[i];
        else if (sz == (long long)A * 4) anc = (const float*)d_in[i];
        else if (sz == B) scl = (const float*)d_in[i];
    }
    float* out = (float*)d_out;

    static bool attr_set = false;
    if (!attr_set) {
        cudaFuncSetAttribute(k_fallback,
                             cudaFuncAttributeMaxDynamicSharedMemorySize,
                             SORT_CAP * (int)sizeof(unsigned long long));
        attr_set = true;
    }

    {
        dim3 grid((N4 + MBLK - 1) / MBLK, B);
        k_main<<<grid, MT>>>(cls);
    }
    k_thresh_scatter<<<B, HBINS>>>();
    k_fallback<<<B, 1024, SORT_CAP * sizeof(unsigned long long)>>>(cls, box, anc);
    {
        dim3 grid(256, B);
        k_binsort<<<grid, 128>>>(box, anc);
    }
    k_nms<<<B, 32>>>(scl, out);
}

// round 9
// speedup vs baseline: 1.1322x; 1.1089x over previous
#include <cuda_runtime.h>
#include <cstdint>

#define B 8
#define A 110484
#define C 90
#define NN (A * C)          /* 9,943,560 per image */
#define N4 (NN / 4)         /* 2,485,890 */
#define TOPK 5000
#define MAXOUT 100
#define CAND_CAP 32768
#define SORT_CAP 16384
#define IOU_T 0.5f

#define SPEC_F 3.0f
#define KEY0 0xC0400000u    /* fkey(3.0f) */
#define HBINS 1024
#define HSHIFT 13
#define FBINS 4096
#define BINMAX 1024         /* per-bin sort capacity */

/* k_main tiling: 256 threads x 4 float4 per block (proven config) */
#define MT 256
#define MV 4
#define MBLK (MT * MV)      /* 1024 float4 per block */

/* ------------------------- scratch (static, no allocs) ------------------ */
/* INVARIANT: g_hist, g_cnt, g_maxck are zero at the start of every launch:
   zero-initialized at load, and every launch restores them to zero. */
__device__ unsigned int       g_hist[B][HBINS];     /* fine bins, keys >= 3.0 */
__device__ unsigned int       g_binpack[B][HBINS];  /* (count<<16)|start      */
__device__ unsigned int       g_thresh[B];
__device__ int                g_T[B];               /* threshold bin          */
__device__ int                g_ok[B];
__device__ int                g_cnt[B];
__device__ unsigned long long g_cand[B][CAND_CAP];
__device__ unsigned long long g_sorted[B][SORT_CAP];
__device__ float4             g_boxes[B][TOPK];
__device__ float              g_scores[B][TOPK];
__device__ int                g_cls[B][TOPK];
__device__ unsigned int       g_maxck[B];           /* fkey(max coord)        */

/* order-preserving float<->uint key */
__device__ __forceinline__ unsigned int fkey(float f) {
    unsigned int u = __float_as_uint(f);
    return (u & 0x80000000u) ? ~u : (u | 0x80000000u);
}
__device__ __forceinline__ float finv(unsigned int k) {
    unsigned int u = (k & 0x80000000u) ? (k ^ 0x80000000u) : ~k;
    return __uint_as_float(u);
}

/* decode one candidate; returns max box coord */
__device__ __forceinline__ float decode_one(int b, int pos, unsigned long long kv,
                                            const float4* __restrict__ bo4,
                                            const float4* __restrict__ an4) {
    unsigned int key = (unsigned int)(kv >> 32);
    unsigned int idx = 0xFFFFFFFFu - (unsigned int)(kv & 0xFFFFFFFFu);
    float val = finv(key);
    unsigned int a = idx / (unsigned int)C;
    int cidx = (int)(idx - a * (unsigned int)C);
    float4 rc = bo4[(size_t)b * A + a];
    float4 an = an4[a];
    float ycA = (an.x + an.z) * 0.5f;
    float xcA = (an.y + an.w) * 0.5f;
    float ha = an.z - an.x;
    float wa = an.w - an.y;
    float w = expf(rc.w) * wa;
    float h = expf(rc.z) * ha;
    float yc = rc.x * ha + ycA;
    float xc = rc.y * wa + xcA;
    float4 box = make_float4(xc - w * 0.5f, yc - h * 0.5f,
                             xc + w * 0.5f, yc + h * 0.5f);
    g_boxes[b][pos] = box;
    g_scores[b][pos] = 1.f / (1.f + expf(-val));
    g_cls[b][pos] = cidx;
    return fmaxf(fmaxf(box.x, box.y), fmaxf(box.z, box.w));
}

/* ------------- pass 1: fused speculative collect + fine hist ------------ */
__device__ __forceinline__ void proc_elem(float val, unsigned int eidx, int b) {
    if (val >= SPEC_F) {
        unsigned int key = __float_as_uint(val) | 0x80000000u; /* val>0 */
        unsigned int bin = (key - KEY0) >> HSHIFT;
        if (bin > HBINS - 1) bin = HBINS - 1;
        atomicAdd(&g_hist[b][bin], 1u);
        int pos = atomicAdd(&g_cnt[b], 1);
        if (pos < CAND_CAP)
            g_cand[b][pos] =
                ((unsigned long long)key << 32) | (0xFFFFFFFFu - eidx);
    }
}
__device__ __forceinline__ void proc_vec(float4 v, unsigned int i, int b) {
    unsigned int base = 4u * i;
    proc_elem(v.x, base + 0u, b);
    proc_elem(v.y, base + 1u, b);
    proc_elem(v.z, base + 2u, b);
    proc_elem(v.w, base + 3u, b);
}

__global__ void __launch_bounds__(MT) k_main(const float* __restrict__ cls) {
    const int b = blockIdx.y;
    const float4* __restrict__ p = (const float4*)(cls + (size_t)b * NN);
    const unsigned int i0 = blockIdx.x * (unsigned)MBLK + threadIdx.x;
    float4 v0, v1, v2, v3;
    const float4 neg = make_float4(-1e30f, -1e30f, -1e30f, -1e30f);
    if ((blockIdx.x + 1) * (unsigned)MBLK <= (unsigned)N4) {
        v0 = p[i0];
        v1 = p[i0 + MT];
        v2 = p[i0 + 2 * MT];
        v3 = p[i0 + 3 * MT];
    } else {
        v0 = (i0          < (unsigned)N4) ? p[i0]          : neg;
        v1 = (i0 +   MT   < (unsigned)N4) ? p[i0 + MT]     : neg;
        v2 = (i0 + 2 * MT < (unsigned)N4) ? p[i0 + 2 * MT] : neg;
        v3 = (i0 + 3 * MT < (unsigned)N4) ? p[i0 + 3 * MT] : neg;
    }
    float m0 = fmaxf(fmaxf(v0.x, v0.y), fmaxf(v0.z, v0.w));
    float m1 = fmaxf(fmaxf(v1.x, v1.y), fmaxf(v1.z, v1.w));
    float m2 = fmaxf(fmaxf(v2.x, v2.y), fmaxf(v2.z, v2.w));
    float m3 = fmaxf(fmaxf(v3.x, v3.y), fmaxf(v3.z, v3.w));
    float m = fmaxf(fmaxf(m0, m1), fmaxf(m2, m3));
    if (m >= SPEC_F) {  /* ~2% of threads */
        proc_vec(v0, i0, b);
        proc_vec(v1, i0 + MT, b);
        proc_vec(v2, i0 + 2 * MT, b);
        proc_vec(v3, i0 + 3 * MT, b);
    }
}

/* --- pass 2: threshold + descending prefix + scatter; resets hist/cnt --- */
__global__ void __launch_bounds__(HBINS) k_thresh_scatter() {
    const int b = blockIdx.x;
    const int tid = threadIdx.x;
    __shared__ unsigned int wsum[32], woff[32], wmax[32];
    __shared__ unsigned int binstart_s[HBINS];
    __shared__ unsigned int binoff_s[HBINS];
    __shared__ int rT;
    __shared__ unsigned int totGe;
    __shared__ int ok_s;
    __shared__ unsigned int th_s;
    __shared__ int cnt_s;

    /* hist in descending-key order; zero it for the next launch */
    unsigned int v = g_hist[b][HBINS - 1 - tid];
    g_hist[b][HBINS - 1 - tid] = 0u;
    unsigned int lane = tid & 31u, w = tid >> 5;
    binoff_s[tid] = 0;
    unsigned int incl = v;
    #pragma unroll
    for (int o = 1; o < 32; o <<= 1) {
        unsigned int t = __shfl_up_sync(0xffffffffu, incl, o);
        if (lane >= (unsigned)o) incl += t;
    }
    if (lane == 31) wsum[w] = incl;
    if (tid == 0) { rT = -1; totGe = 0; }
    __syncthreads();
    if (tid == 0) {
        unsigned int acc = 0;
        for (int i = 0; i < 32; i++) { woff[i] = acc; acc += wsum[i]; }
    }
    __syncthreads();
    unsigned int excl = woff[w] + incl - v;
    binstart_s[HBINS - 1 - tid] = excl;
    g_binpack[b][HBINS - 1 - tid] = (v << 16) | excl;  /* count|start */
    if (v > 0 && excl < TOPK && excl + v >= TOPK) { rT = tid; totGe = excl + v; }
    __syncthreads();
    int r = rT;
    unsigned int mv = (r >= 0 && tid <= r) ? v : 0;
    #pragma unroll
    for (int o = 16; o > 0; o >>= 1)
        mv = max(mv, __shfl_down_sync(0xffffffffu, mv, o));
    if (lane == 0) wmax[w] = mv;
    __syncthreads();
    if (tid == 0) {
        unsigned int mb = 0;
        for (int i = 0; i < 32; i++) mb = max(mb, wmax[i]);
        int cnt = g_cnt[b];
        g_cnt[b] = 0;                 /* reset for next launch */
        cnt_s = cnt;
        int ok = (r >= 0) && (cnt <= CAND_CAP) && (totGe <= SORT_CAP) &&
                 (mb <= BINMAX);
        g_ok[b] = ok;
        ok_s = ok;
        if (ok) {
            int binT = HBINS - 1 - r;
            g_T[b] = binT;
            th_s = KEY0 + ((unsigned int)binT << HSHIFT);
            g_thresh[b] = th_s;
        }
    }
    __syncthreads();
    if (!ok_s) return;

    /* scatter candidates to bin slot ranges (smem cursors) */
    const unsigned int th = th_s;
    int cnt = cnt_s;
    for (int i = tid; i < cnt; i += HBINS) {
        unsigned long long kv = g_cand[b][i];
        unsigned int key = (unsigned int)(kv >> 32);
        if (key >= th) {
            unsigned int bin = (key - KEY0) >> HSHIFT;
            if (bin > HBINS - 1) bin = HBINS - 1;
            unsigned int pos = binstart_s[bin] + atomicAdd(&binoff_s[bin], 1u);
            g_sorted[b][pos] = kv;
        }
    }
}

/* ------- fallback: entire pipeline in one block per image (never hot) ---- */
__global__ void __launch_bounds__(1024) k_fallback(const float* __restrict__ cls,
                                                   const float* __restrict__ box_out,
                                                   const float* __restrict__ anchors) {
    extern __shared__ unsigned long long sdyn[];  /* 128 KB */
    const int b = blockIdx.x;
    if (g_ok[b]) return;
    const int tid = threadIdx.x;
    unsigned int* h = (unsigned int*)sdyn;  /* FBINS counters (reused later) */
    for (int i = tid; i < FBINS; i += 1024) h[i] = 0;
    __syncthreads();
    const float4* p = (const float4*)(cls + (size_t)b * NN);
    for (int i = tid; i < N4; i += 1024) {
        float4 v = p[i];
        atomicAdd(&h[fkey(v.x) >> 20], 1u);
        atomicAdd(&h[fkey(v.y) >> 20], 1u);
        atomicAdd(&h[fkey(v.z) >> 20], 1u);
        atomicAdd(&h[fkey(v.w) >> 20], 1u);
    }
    __syncthreads();
    __shared__ unsigned int th_sh;
    __shared__ int scnt;
    if (tid == 0) {
        unsigned int acc = 0;
        int T = 0;
        for (int bin = FBINS - 1; bin >= 0; bin--) {
            acc += h[bin];
            if (acc >= TOPK) { T = bin; break; }
        }
        th_sh = ((unsigned int)T) << 20;
        scnt = 0;
    }
    __syncthreads();
    const unsigned int th = th_sh;
    __syncthreads();  /* all threads read th before sdyn reuse */
    for (int i = tid; i < N4; i += 1024) {
        float4 v = p[i];
        unsigned int base = 4u * (unsigned int)i;
        float vals[4] = {v.x, v.y, v.z, v.w};
        #pragma unroll
        for (int e = 0; e < 4; e++) {
            unsigned int k = fkey(vals[e]);
            if (k >= th) {
                int pos = atomicAdd(&scnt, 1);
                if (pos < SORT_CAP)
                    sdyn[pos] = ((unsigned long long)k << 32) |
                                (0xFFFFFFFFu - (base + (unsigned)e));
            }
        }
    }
    __syncthreads();
    int c2 = scnt;
    if (c2 > SORT_CAP) c2 = SORT_CAP;
    const int nn = (c2 <= 8192) ? 8192 : SORT_CAP;
    for (int i = c2 + tid; i < nn; i += 1024) sdyn[i] = 0ULL;
    __syncthreads();
    for (unsigned int k = 2; k <= (unsigned int)nn; k <<= 1) {
        for (unsigned int j = k >> 1; j > 0; j >>= 1) {
            for (int i = tid; i < nn; i += 1024) {
                unsigned int ixj = (unsigned int)i ^ j;
                if (ixj > (unsigned int)i) {
                    bool up = ((i & k) == 0);
                    unsigned long long a = sdyn[i], c = sdyn[ixj];
                    bool sw = up ? (a < c) : (a > c);
                    if (sw) { sdyn[i] = c; sdyn[ixj] = a; }
                }
            }
            __syncthreads();
        }
    }
    const float4* bo4 = (const float4*)box_out;
    const float4* an4 = (const float4*)anchors;
    float localmax = -1e30f;
    for (int i = tid; i < TOPK; i += 1024) {
        unsigned long long kv = sdyn[i];
        if (kv == 0ULL) {
            g_boxes[b][i] = make_float4(0.f, 0.f, 0.f, 0.f);
            g_scores[b][i] = 0.f;
            g_cls[b][i] = 0;
        } else {
            localmax = fmaxf(localmax, decode_one(b, i, kv, bo4, an4));
        }
    }
    #pragma unroll
    for (int o = 16; o > 0; o >>= 1)
        localmax = fmaxf(localmax, __shfl_xor_sync(0xffffffffu, localmax, o));
    if ((tid & 31) == 0) atomicMax(&g_maxck[b], fkey(localmax));
}

/* --------- pass 3: per-bin rank sort + fused decode ---------------------- */
__global__ void __launch_bounds__(128) k_binsort(const float* __restrict__ box_out,
                                                 const float* __restrict__ anchors) {
    const int bin = blockIdx.x;
    const int b = blockIdx.y;
    if (!g_ok[b]) return;
    if (bin < g_T[b]) return;
    const unsigned int pk = g_binpack[b][bin];
    const unsigned int c = pk >> 16;
    if (c == 0) return;
    const unsigned int start = pk & 0xFFFFu;
    if (start >= TOPK) return;
    __shared__ unsigned long long s[BINMAX];
    const int tid = threadIdx.x;
    for (unsigned int i = tid; i < c; i += 128)
        s[i] = g_sorted[b][start + i];
    __syncthreads();
    /* rank sort: rank = #elements greater (keys unique via packed index) */
    const float4* bo4 = (const float4*)box_out;
    const float4* an4 = (const float4*)anchors;
    float localmax = -1e30f;
    for (unsigned int i = tid; i < c; i += 128) {
        unsigned long long me = s[i];
        unsigned int rank = 0;
        for (unsigned int j = 0; j < c; j++) rank += (s[j] > me);
        unsigned int pos = start + rank;
        if (pos < TOPK)
            localmax = fmaxf(localmax, decode_one(b, (int)pos, me, bo4, an4));
    }
    #pragma unroll
    for (int o = 16; o > 0; o >>= 1)
        localmax = fmaxf(localmax, __shfl_xor_sync(0xffffffffu, localmax, o));
    if ((tid & 31) == 0) atomicMax(&g_maxck[b], fkey(localmax));
}

/* ------- pass 4: batched warp NMS + output; resets g_maxck --------------- */
__global__ void k_nms(const float* __restrict__ img_scale, float* __restrict__ out) {
    const int b = blockIdx.x;
    const int l = threadIdx.x;     /* 32 threads: one warp per image */
    __shared__ float4 skb[MAXOUT]; /* kept offset boxes */
    __shared__ float  ska[MAXOUT]; /* kept areas        */

    const float maxc1 = finv(g_maxck[b]) + 1.0f;
    if (l == 0) g_maxck[b] = 0u;   /* reset for next launch */
    const float scale = img_scale[b];
    int K = 0;

    for (int base = 0; base < TOPK && K < MAXOUT; base += 32) {
        const int m = (TOPK - base < 32) ? (TOPK - base) : 32;
        const bool active = l < m;
        const int ci = base + (active ? l : 0);
        float4 bx = g_boxes[b][ci];
        float sc = g_scores[b][ci];
        int cidx = g_cls[b][ci];
        float off = (float)cidx * maxc1;
        float4 nb = make_float4(bx.x + off, bx.y + off, bx.z + off, bx.w + off);
        float area = (nb.z - nb.x) * (nb.w - nb.y);

        /* parallel vs-kept check: lane l tests its own candidate */
        bool ovk = !active;
        for (int j = 0; j < K; j++) {
            float4 kb = skb[j];
            float w = fminf(nb.z, kb.z) - fmaxf(nb.x, kb.x);
            float h = fminf(nb.w, kb.w) - fmaxf(nb.y, kb.y);
            w = fmaxf(w, 0.f); h = fmaxf(h, 0.f);
            float inter = w * h;
            if (inter > 0.f && inter / (area + ska[j] - inter) > IOU_T)
                ovk = true;
        }

        /* pairwise overlaps within batch (bit j of ovp = overlap with cand j) */
        unsigned int ovp = 0;
        #pragma unroll 8
        for (int j = 0; j < 32; j++) {
            float xx = __shfl_sync(0xffffffffu, nb.x, j);
            float yy = __shfl_sync(0xffffffffu, nb.y, j);
            float zz = __shfl_sync(0xffffffffu, nb.z, j);
            float ww = __shfl_sync(0xffffffffu, nb.w, j);
            float aj = __shfl_sync(0xffffffffu, area, j);
            float w = fminf(nb.z, zz) - fmaxf(nb.x, xx);
            float h = fminf(nb.w, ww) - fmaxf(nb.y, yy);
            w = fmaxf(w, 0.f); h = fmaxf(h, 0.f);
            float inter = w * h;
            if (inter > 0.f && inter / (area + aj - inter) > IOU_T)
                ovp |= 1u << j;
        }

        /* sequential greedy resolve over the batch (warp-uniform) */
        const unsigned int ovk_all = __ballot_sync(0xffffffffu, ovk);
        unsigned int acc = 0;
        for (int j = 0; j < m; j++) {
            unsigned int mask_j = __shfl_sync(0xffffffffu, ovp, j);
            bool sup = ((ovk_all >> j) & 1u) || ((mask_j & acc) != 0u);
            if (!sup) acc |= 1u << j;
        }

        /* append accepted (in order) up to the MAXOUT cap */
        const int navail = MAXOUT - K;
        const bool accme = active && ((acc >> l) & 1u);
        const int myrank = __popc(acc & ((1u << l) - 1u));
        if (accme && myrank < navail) {
            int pos = K + myrank;
            skb[pos] = nb;
            ska[pos] = area;
            float* o = out + ((size_t)b * MAXOUT + pos) * 6;
            o[0] = bx.x * scale;
            o[1] = bx.y * scale;
            o[2] = bx.z * scale;
            o[3] = bx.w * scale;
            o[4] = sc;
            o[5] = (float)(cidx + 1);
        }
        int nacc = __popc(acc);
        K += (nacc < navail) ? nacc : navail;
        __syncwarp();
    }
    /* pad invalid rows */
    for (int r = K + l; r < MAXOUT; r += 32) {
        float* o = out + ((size_t)b * MAXOUT + r) * 6;
        o[0] = 0.f; o[1] = 0.f; o[2] = 0.f; o[3] = 0.f;
        o[4] = 0.f; o[5] = -1.f;
    }
}

/* ------------------------------ launcher -------------------------------- */
extern "C" void kernel_launch(void* const* d_in, const int* in_sizes, int n_in,
                              void* d_out, int out_size) {
    const float* cls = nullptr;
    const float* box = nullptr;
    const float* anc = nullptr;
    const float* scl = nullptr;
    for (int i = 0; i < n_in; i++) {
        long long sz = in_sizes[i];
        if (sz == (long long)B * NN) cls = (const float*)d_in[i];
        else if (sz == (long long)B * A * 4) box = (const float*)d_in[i];
        else if (sz == (long long)A * 4) anc = (const float*)d_in[i];
        else if (sz == B) scl = (const float*)d_in[i];
    }
    float* out = (float*)d_out;

    static bool attr_set = false;
    if (!attr_set) {
        cudaFuncSetAttribute(k_fallback,
                             cudaFuncAttributeMaxDynamicSharedMemorySize,
                             SORT_CAP * (int)sizeof(unsigned long long));
        attr_set = true;
    }

    {
        dim3 grid((N4 + MBLK - 1) / MBLK, B);
        k_main<<<grid, MT>>>(cls);
    }
    k_thresh_scatter<<<B, HBINS>>>();
    k_fallback<<<B, 1024, SORT_CAP * sizeof(unsigned long long)>>>(cls, box, anc);
    {
        dim3 grid(HBINS, B);
        k_binsort<<<grid, 128>>>(box, anc);
    }
    k_nms<<<B, 32>>>(scl, out);
}